// round 10
// baseline (speedup 1.0000x reference)
#include <cuda_runtime.h>
#include <math.h>
#include <stdint.h>

#ifndef M_PI
#define M_PI 3.14159265358979323846
#endif

// Intermediate yr, shape [4][340][256][256] fp32 (~357 MB), device global.
__device__ float g_yr[89128960];
// W_in transposed: WinT[c][o], 64 x 340.
__device__ float g_WinT[21760];
// 1 if quant is all-ones (DCT->quant->IDCT is identity), else 0.
__device__ int g_ones;

typedef unsigned long long ull;

// ---- packed f32x2 helpers ----
__device__ __forceinline__ ull pk(float x, float y) {
    ull r;
    asm("mov.b64 %0, {%1, %2};" : "=l"(r) : "r"(__float_as_int(x)), "r"(__float_as_int(y)));
    return r;
}
__device__ __forceinline__ void fma2(ull& d, ull a, ull b) {
    asm("fma.rn.f32x2 %0, %1, %2, %0;" : "+l"(d) : "l"(a), "l"(b));
}
__device__ __forceinline__ float2 upk(ull v) {
    int lo, hi;
    asm("mov.b64 {%0, %1}, %2;" : "=r"(lo), "=r"(hi) : "l"(v));
    return make_float2(__int_as_float(lo), __int_as_float(hi));
}

// ---- cp.async helpers ----
__device__ __forceinline__ void cp16(uint32_t dst, uint64_t gsrc, unsigned sz) {
    asm volatile("cp.async.cg.shared.global [%0], [%1], 16, %2;"
                 :: "r"(dst), "l"(gsrc), "r"(sz));
}
__device__ __forceinline__ void cp_commit() {
    asm volatile("cp.async.commit_group;" ::: "memory");
}
__device__ __forceinline__ void cp_wait1() {
    asm volatile("cp.async.wait_group 1;" ::: "memory");
}
__device__ __forceinline__ uint32_t smem_u32(const void* p) {
    uint32_t a;
    asm("{ .reg .u64 t; cvta.to.shared.u64 t, %1; cvt.u32.u64 %0, t; }"
        : "=r"(a) : "l"(p));
    return a;
}
__device__ __forceinline__ uint64_t gmem_u64(const void* p) {
    uint64_t a;
    asm("cvta.to.global.u64 %0, %1;" : "=l"(a) : "l"(p));
    return a;
}

// ---------------------------------------------------------------------------
// Setup kernels: flag init/check + W_in transpose.
// ---------------------------------------------------------------------------
__global__ void kinit() {
    if (threadIdx.x == 0) g_ones = 1;
}
__global__ void kcheck(const float* __restrict__ quant) {
    int i = blockIdx.x * 256 + threadIdx.x;   // 85*256 == 21760
    if (quant[i] != 1.0f) atomicExch(&g_ones, 0);
}
__global__ void ktrans(const float* __restrict__ Win) {
    int i = blockIdx.x * 256 + threadIdx.x;   // 85*256 == 21760
    int o = i >> 6, c = i & 63;
    g_WinT[c * 340 + o] = Win[i];
}

// ---------------------------------------------------------------------------
// Fast path kernel A3 (quant == ones): proj_in register-blocked f32x2 GEMM
// with double-buffered cp.async weight staging from transposed g_WinT.
// CTA = 4x64 pixel tile, 256 threads; 6 chunks of 64 outputs (last zero-
// padded past 340). Dyn smem: xs 64KB + Wk[2][4096] 32KB = 98304 B.
// ---------------------------------------------------------------------------
__global__ void __launch_bounds__(256, 2) kernA3(
    const float* __restrict__ x)
{
    if (!*(volatile int*)&g_ones) return;

    extern __shared__ float sm[];
    float* xs = sm;            // [c][p]
    float* Wk = sm + 16384;    // [2][64][64]

    const int t = threadIdx.x;
    const int b = blockIdx.z;
    const int row0 = blockIdx.y * 4;
    const int col0 = blockIdx.x * 64;

    // Stage x tile: 64 ch x 256 px, vectorized float4.
    {
        const float* xb = x + ((size_t)b << 22);
        #pragma unroll
        for (int k = 0; k < 16; k++) {
            int i = t + k * 256;
            int c = i >> 6, q = i & 63;
            int r = q >> 4, cc = (q & 15) * 4;
            float4 v = *(const float4*)(xb + ((size_t)c * 256 + row0 + r) * 256 + col0 + cc);
            *(float4*)(xs + c * 256 + q * 4) = v;
        }
    }

    const uint64_t wT = gmem_u64(g_WinT);
    const uint32_t wkS = smem_u32(Wk);

    // Stage chunk k's weights into buffer (k&1): 16 floats/thread = 4x cp16.
    auto stageW = [&](int k) {
        uint32_t dst = wkS + (uint32_t)(k & 1) * 16384u + (uint32_t)t * 64u;
        int o0 = k * 64;
        #pragma unroll
        for (int j = 0; j < 4; j++) {
            int i = t * 16 + j * 4;
            int c = i >> 6, o = i & 63;
            unsigned sz = (o0 + o < 340) ? 16u : 0u;   // o%4==0, 340%4==0
            cp16(dst + (uint32_t)j * 16u, wT + ((uint64_t)c * 340 + o0 + o) * 4, sz);
        }
    };

    stageW(0); cp_commit();

    const int po = t & 31;
    const int oo = t >> 5;
    const int rA = po >> 4, cA = (po * 4) & 63;

    for (int k = 0; k < 6; k++) {
        __syncthreads();                 // buf (k+1)&1 readers (chunk k-1) done
        if (k < 5) stageW(k + 1);
        cp_commit();
        cp_wait1();                      // group k complete
        __syncthreads();                 // group-k data visible CTA-wide

        const float* wb = Wk + (k & 1) * 4096;
        bool active = (k < 5) || (oo * 8 < 20);   // tail: warps 0..2 only
        if (active) {
            ull acc[8][4];
            #pragma unroll
            for (int o = 0; o < 8; o++)
                #pragma unroll
                for (int j = 0; j < 4; j++) acc[o][j] = 0ull;

            #pragma unroll 4
            for (int c = 0; c < 64; c++) {
                float4 xa  = *(const float4*)(xs + c * 256 + po * 4);
                float4 xb4 = *(const float4*)(xs + c * 256 + po * 4 + 128);
                ull x0 = pk(xa.x, xa.y),   x1 = pk(xa.z, xa.w);
                ull x2 = pk(xb4.x, xb4.y), x3 = pk(xb4.z, xb4.w);
                float4 wa = *(const float4*)(wb + c * 64 + oo * 8);
                float4 wq = *(const float4*)(wb + c * 64 + oo * 8 + 4);
                float wv[8] = {wa.x, wa.y, wa.z, wa.w, wq.x, wq.y, wq.z, wq.w};
                #pragma unroll
                for (int o = 0; o < 8; o++) {
                    ull wd = pk(wv[o], wv[o]);
                    fma2(acc[o][0], wd, x0);
                    fma2(acc[o][1], wd, x1);
                    fma2(acc[o][2], wd, x2);
                    fma2(acc[o][3], wd, x3);
                }
            }

            #pragma unroll
            for (int o = 0; o < 8; o++) {
                int og = k * 64 + oo * 8 + o;
                if (og < 340) {
                    float2 p0 = upk(acc[o][0]), p1 = upk(acc[o][1]);
                    float2 p2 = upk(acc[o][2]), p3 = upk(acc[o][3]);
                    size_t pl = ((size_t)b * 340 + og) * 65536;
                    *(float4*)(g_yr + pl + (size_t)(row0 + rA) * 256 + col0 + cA) =
                        make_float4(p0.x, p0.y, p1.x, p1.y);
                    *(float4*)(g_yr + pl + (size_t)(row0 + rA + 2) * 256 + col0 + cA) =
                        make_float4(p2.x, p2.y, p3.x, p3.y);
                }
            }
        }
    }
}

// ---------------------------------------------------------------------------
// Fallback kernel A (quant != ones): fused proj_in + DCT + quant + IDCT.
// ---------------------------------------------------------------------------
__global__ void __launch_bounds__(256, 2) kernA(
    const float* __restrict__ x, const float* __restrict__ Win,
    const float* __restrict__ quant)
{
    if (*(volatile int*)&g_ones) return;

    extern __shared__ float sm[];
    float* xs   = sm;
    float* bufA = sm + 16384;
    float* bufB = sm + 18688;
    float* Wk   = sm + 20992;
    float* qk   = sm + 21504;
    float* Ms   = sm + 22016;

    const int t  = threadIdx.x;
    const int b  = blockIdx.z;
    const int tx = blockIdx.x, ty = blockIdx.y;
    const int lx = t & 15, ly = t >> 4;
    const int gx = tx * 16 + lx, gy = ty * 16 + ly;

    if (t < 64) {
        int i = t >> 3, j = t & 7;
        Ms[t] = (i == 0) ? 0.3535533905932738f
                         : 0.5f * cosf((float)M_PI * (float)(i * (2 * j + 1)) / 16.0f);
    }
    {
        const float* xb = x + ((size_t)b << 22);
        int pofs = gy * 256 + gx;
        #pragma unroll
        for (int c = 0; c < 64; c++)
            xs[c * 256 + t] = xb[c * 65536 + pofs];
    }

    const int ch  = t >> 5;
    const int pat = (t >> 3) & 3;
    const int ln  = t & 7;
    float* pA = bufA + ch * 288 + pat * 72;
    float* pB = bufB + ch * 288 + pat * 72;

    const int patc = ((ly >> 3) << 1) + (lx >> 3);
    const int rr = ly & 7, cc = lx & 7;
    float* convDst = bufA + patc * 72 + rr * 9 + cc;

    for (int o0 = 0; o0 < 340; o0 += 8) {
        #pragma unroll
        for (int r = 0; r < 2; r++) {
            int idx = t + r * 256;
            int c = idx >> 3, o = idx & 7;
            Wk[idx] = (o0 + o < 340) ? Win[(o0 + o) * 64 + c] : 0.0f;
            int o2 = idx >> 6, rc = idx & 63;
            qk[idx] = (o0 + o2 < 340) ? quant[(o0 + o2) * 64 + rc] : 0.0f;
        }
        __syncthreads();

        float acc[8] = {0.f, 0.f, 0.f, 0.f, 0.f, 0.f, 0.f, 0.f};
        #pragma unroll 8
        for (int c = 0; c < 64; c++) {
            float  xv = xs[c * 256 + t];
            float4 w0 = *reinterpret_cast<const float4*>(Wk + c * 8);
            float4 w1 = *reinterpret_cast<const float4*>(Wk + c * 8 + 4);
            acc[0] += w0.x * xv; acc[1] += w0.y * xv;
            acc[2] += w0.z * xv; acc[3] += w0.w * xv;
            acc[4] += w1.x * xv; acc[5] += w1.y * xv;
            acc[6] += w1.z * xv; acc[7] += w1.w * xv;
        }
        #pragma unroll
        for (int o = 0; o < 8; o++) convDst[o * 288] = acc[o];
        __syncthreads();

        float v[8];
        #pragma unroll
        for (int p = 0; p < 8; p++) v[p] = pA[p * 9 + ln];
        #pragma unroll
        for (int i = 0; i < 8; i++) {
            float s = 0.f;
            #pragma unroll
            for (int p = 0; p < 8; p++) s += Ms[i * 8 + p] * v[p];
            pB[i * 9 + ln] = s;
        }
        __syncthreads();

        #pragma unroll
        for (int q = 0; q < 8; q++) v[q] = pB[ln * 9 + q];
        #pragma unroll
        for (int j = 0; j < 8; j++) {
            float s = 0.f;
            #pragma unroll
            for (int q = 0; q < 8; q++) s += v[q] * Ms[j * 8 + q];
            pA[ln * 9 + j] = s * qk[ch * 64 + ln * 8 + j];
        }
        __syncthreads();

        #pragma unroll
        for (int p = 0; p < 8; p++) v[p] = pA[p * 9 + ln];
        #pragma unroll
        for (int i = 0; i < 8; i++) {
            float s = 0.f;
            #pragma unroll
            for (int p = 0; p < 8; p++) s += Ms[p * 8 + i] * v[p];
            pB[i * 9 + ln] = s;
        }
        __syncthreads();

        #pragma unroll
        for (int q = 0; q < 8; q++) v[q] = pB[ln * 9 + q];
        int o = o0 + ch;
        if (o < 340) {
            float r8[8];
            #pragma unroll
            for (int j = 0; j < 8; j++) {
                float s = 0.f;
                #pragma unroll
                for (int q = 0; q < 8; q++) s += v[q] * Ms[q * 8 + j];
                r8[j] = s;
            }
            int py = pat >> 1, px = pat & 1;
            size_t base = (((size_t)b * 340 + o) * 256 +
                           (size_t)(ty * 16 + py * 8 + ln)) * 256 +
                          (size_t)(tx * 16 + px * 8);
            float4* dst = reinterpret_cast<float4*>(g_yr + base);
            dst[0] = make_float4(r8[0], r8[1], r8[2], r8[3]);
            dst[1] = make_float4(r8[4], r8[5], r8[6], r8[7]);
        }
    }
}

// ---------------------------------------------------------------------------
// Kernel B6: fused depthwise 3x3 + exact-GELU gate + proj_out.
// NO smem tiling, NO barriers in main loop: each thread reads its own 3x3
// neighborhoods directly from gmem (L1-cached; neighbors shared by warp).
// Clamped addresses + per-tap zero mask handle image borders.
// Dyn smem: Wo 43520 + pdw 12240 = 55760 B.
// ---------------------------------------------------------------------------
__global__ void __launch_bounds__(256, 2) kernB6(
    const float* __restrict__ Wdw, const float* __restrict__ Wout,
    float* __restrict__ out)
{
    extern __shared__ float smB[];
    float*  Wo  = smB;                      // [oh][64]
    float2* pdw = (float2*)(smB + 10880);   // [oh][9]  packed {w1,w2}

    const int t  = threadIdx.x;
    const int b  = blockIdx.z;
    const int tx = blockIdx.x, ty = blockIdx.y;
    const int lx = t & 15, ly = t >> 4;
    const int gx = tx * 16 + lx, gy = ty * 16 + ly;

    for (int i = t; i < 10880; i += 256)
        Wo[i] = Wout[(i & 63) * 170 + (i >> 6)];
    for (int i = t; i < 1530; i += 256) {
        int oh = i / 9, k = i - oh * 9;
        pdw[i] = make_float2(Wdw[oh * 9 + k], Wdw[(oh + 170) * 9 + k]);
    }
    __syncthreads();

    // Per-thread 3x3 tap geometry (clamped offsets + validity masks).
    int off9[9];
    bool ok9[9];
    #pragma unroll
    for (int ky = 0; ky < 3; ky++) {
        int yy = gy + ky - 1;
        int yyc = yy < 0 ? 0 : (yy > 255 ? 255 : yy);
        bool vy = ((unsigned)yy < 256u);
        #pragma unroll
        for (int kx = 0; kx < 3; kx++) {
            int xx = gx + kx - 1;
            int xxc = xx < 0 ? 0 : (xx > 255 ? 255 : xx);
            off9[ky * 3 + kx] = yyc * 256 + xxc;
            ok9[ky * 3 + kx] = vy && ((unsigned)xx < 256u);
        }
    }

    const float* base1 = g_yr + (size_t)b * 340 * 65536;
    const float* base2 = base1 + (size_t)170 * 65536;

    ull acc[32];
    #pragma unroll
    for (int j = 0; j < 32; j++) acc[j] = 0ull;

    const ull*        pdwu = (const ull*)pdw;
    const ulonglong2* Wo2  = (const ulonglong2*)Wo;

    for (int oh = 0; oh < 170; oh++) {
        const float* p1 = base1 + (size_t)oh * 65536;
        const float* p2 = base2 + (size_t)oh * 65536;

        // Load 3x3 neighborhoods of both planes (18 independent LDGs).
        float va[9], vb[9];
        #pragma unroll
        for (int k = 0; k < 9; k++) {
            va[k] = __ldg(p1 + off9[k]);
            vb[k] = __ldg(p2 + off9[k]);
        }

        ull d2 = 0ull;
        #pragma unroll
        for (int k = 0; k < 9; k++) {
            ull v = ok9[k] ? pk(va[k], vb[k]) : 0ull;
            fma2(d2, v, pdwu[oh * 9 + k]);
        }
        float2 d = upk(d2);
        float g = 0.5f * d.x * (1.0f + erff(d.x * 0.7071067811865476f)) * d.y;
        ull gg = pk(g, g);

        #pragma unroll
        for (int j4 = 0; j4 < 16; j4++) {
            ulonglong2 w2 = Wo2[oh * 16 + j4];
            fma2(acc[j4 * 2 + 0], gg, w2.x);
            fma2(acc[j4 * 2 + 1], gg, w2.y);
        }
    }

    size_t obase = ((size_t)b * 64) * 65536 + (size_t)gy * 256 + (size_t)gx;
    #pragma unroll
    for (int j = 0; j < 32; j++) {
        float2 v = upk(acc[j]);
        out[obase + (size_t)(j * 2 + 0) * 65536] = v.x;
        out[obase + (size_t)(j * 2 + 1) * 65536] = v.y;
    }
}

// ---------------------------------------------------------------------------
extern "C" void kernel_launch(void* const* d_in, const int* in_sizes, int n_in,
                              void* d_out, int out_size)
{
    (void)in_sizes; (void)n_in; (void)out_size;
    const float* x     = (const float*)d_in[0];  // [4,64,256,256]
    const float* Win   = (const float*)d_in[1];  // [340,64]
    const float* Wdw   = (const float*)d_in[2];  // [340,1,3,3]
    const float* quant = (const float*)d_in[3];  // [340,1,1,8,8]
    const float* Wout  = (const float*)d_in[4];  // [64,170]
    float* out = (float*)d_out;                  // [4,64,256,256]

    static int attr_done = 0;
    if (!attr_done) {
        cudaFuncSetAttribute(kernA,  cudaFuncAttributeMaxDynamicSharedMemorySize, 88320);
        cudaFuncSetAttribute(kernA3, cudaFuncAttributeMaxDynamicSharedMemorySize, 98304);
        cudaFuncSetAttribute(kernB6, cudaFuncAttributeMaxDynamicSharedMemorySize, 55760);
        attr_done = 1;
    }

    kinit<<<1, 32>>>();
    kcheck<<<85, 256>>>(quant);
    ktrans<<<85, 256>>>(Win);

    dim3 gOld(16, 16, 4), blk(256);
    kernA<<<gOld, blk, 88320>>>(x, Win, quant);   // runs only if quant != 1

    dim3 gA2(4, 64, 4);
    kernA3<<<gA2, blk, 98304>>>(x);               // runs only if quant == 1

    kernB6<<<gOld, blk, 55760>>>(Wdw, Wout, out);
}

// round 12
// speedup vs baseline: 1.1367x; 1.1367x over previous
#include <cuda_runtime.h>
#include <math.h>
#include <stdint.h>

#ifndef M_PI
#define M_PI 3.14159265358979323846
#endif

// Intermediate yr, shape [4][340][256][256] fp32 (~357 MB), device global.
__device__ float g_yr[89128960];
// 1 if quant is all-ones (DCT->quant->IDCT is identity), else 0.
__device__ int g_ones;

typedef unsigned long long ull;

// ---- packed f32x2 helpers ----
__device__ __forceinline__ ull pk(float x, float y) {
    ull r;
    asm("mov.b64 %0, {%1, %2};" : "=l"(r) : "r"(__float_as_int(x)), "r"(__float_as_int(y)));
    return r;
}
__device__ __forceinline__ void fma2(ull& d, ull a, ull b) {
    asm("fma.rn.f32x2 %0, %1, %2, %0;" : "+l"(d) : "l"(a), "l"(b));
}
__device__ __forceinline__ float2 upk(ull v) {
    int lo, hi;
    asm("mov.b64 {%0, %1}, %2;" : "=r"(lo), "=r"(hi) : "l"(v));
    return make_float2(__int_as_float(lo), __int_as_float(hi));
}

// ---- cp.async helpers ----
__device__ __forceinline__ void cp16(uint32_t dst, uint64_t gsrc, unsigned sz) {
    asm volatile("cp.async.cg.shared.global [%0], [%1], 16, %2;"
                 :: "r"(dst), "l"(gsrc), "r"(sz));
}
__device__ __forceinline__ void cp_commit() {
    asm volatile("cp.async.commit_group;" ::: "memory");
}
__device__ __forceinline__ void cp_wait2() {
    asm volatile("cp.async.wait_group 2;" ::: "memory");
}
__device__ __forceinline__ uint32_t smem_u32(const void* p) {
    uint32_t a;
    asm("{ .reg .u64 t; cvta.to.shared.u64 t, %1; cvt.u32.u64 %0, t; }"
        : "=r"(a) : "l"(p));
    return a;
}
__device__ __forceinline__ uint64_t gmem_u64(const void* p) {
    uint64_t a;
    asm("cvta.to.global.u64 %0, %1;" : "=l"(a) : "l"(p));
    return a;
}

// ---------------------------------------------------------------------------
// Flag kernels: detect quant == all-ones.
// ---------------------------------------------------------------------------
__global__ void kinit() {
    if (threadIdx.x == 0) g_ones = 1;
}
__global__ void kcheck(const float* __restrict__ quant) {
    int i = blockIdx.x * 256 + threadIdx.x;   // 85*256 == 21760
    if (quant[i] != 1.0f) atomicExch(&g_ones, 0);
}

// ---------------------------------------------------------------------------
// Fast path kernel A2 (quant == ones): proj_in register-blocked f32x2 GEMM.
// (R9 version, measured 290 us.)
// ---------------------------------------------------------------------------
__global__ void __launch_bounds__(256, 2) kernA2(
    const float* __restrict__ x, const float* __restrict__ Win)
{
    if (!*(volatile int*)&g_ones) return;

    extern __shared__ float sm[];
    float* xs = sm;            // [c][p]
    float* Wk = sm + 16384;    // [c][o] transposed chunk

    const int t = threadIdx.x;
    const int b = blockIdx.z;
    const int row0 = blockIdx.y * 4;
    const int col0 = blockIdx.x * 64;

    {
        const float* xb = x + ((size_t)b << 22);
        #pragma unroll
        for (int k = 0; k < 16; k++) {
            int i = t + k * 256;
            int c = i >> 6, q = i & 63;
            int r = q >> 4, cc = (q & 15) * 4;
            float4 v = *(const float4*)(xb + ((size_t)c * 256 + row0 + r) * 256 + col0 + cc);
            *(float4*)(xs + c * 256 + q * 4) = v;
        }
    }

    const int po = t & 31;
    const int oo = t >> 5;
    const int rA = po >> 4, cA = (po * 4) & 63;

    for (int o0 = 0; o0 < 320; o0 += 64) {
        __syncthreads();
        #pragma unroll
        for (int k = 0; k < 16; k++) {
            int i = t + k * 256;
            int c = i >> 6, o = i & 63;
            Wk[i] = Win[(o0 + o) * 64 + c];
        }
        __syncthreads();

        ull acc[8][4];
        #pragma unroll
        for (int o = 0; o < 8; o++)
            #pragma unroll
            for (int j = 0; j < 4; j++) acc[o][j] = 0ull;

        #pragma unroll 4
        for (int c = 0; c < 64; c++) {
            float4 xa  = *(const float4*)(xs + c * 256 + po * 4);
            float4 xb4 = *(const float4*)(xs + c * 256 + po * 4 + 128);
            ull x0 = pk(xa.x, xa.y),   x1 = pk(xa.z, xa.w);
            ull x2 = pk(xb4.x, xb4.y), x3 = pk(xb4.z, xb4.w);
            float4 wa = *(const float4*)(Wk + c * 64 + oo * 8);
            float4 wb = *(const float4*)(Wk + c * 64 + oo * 8 + 4);
            float wv[8] = {wa.x, wa.y, wa.z, wa.w, wb.x, wb.y, wb.z, wb.w};
            #pragma unroll
            for (int o = 0; o < 8; o++) {
                ull wd = pk(wv[o], wv[o]);
                fma2(acc[o][0], wd, x0);
                fma2(acc[o][1], wd, x1);
                fma2(acc[o][2], wd, x2);
                fma2(acc[o][3], wd, x3);
            }
        }

        #pragma unroll
        for (int o = 0; o < 8; o++) {
            int og = o0 + oo * 8 + o;
            float2 p0 = upk(acc[o][0]), p1 = upk(acc[o][1]);
            float2 p2 = upk(acc[o][2]), p3 = upk(acc[o][3]);
            size_t pl = ((size_t)b * 340 + og) * 65536;
            *(float4*)(g_yr + pl + (size_t)(row0 + rA) * 256 + col0 + cA) =
                make_float4(p0.x, p0.y, p1.x, p1.y);
            *(float4*)(g_yr + pl + (size_t)(row0 + rA + 2) * 256 + col0 + cA) =
                make_float4(p2.x, p2.y, p3.x, p3.y);
        }
    }

    // tail chunk: outputs 320..339
    __syncthreads();
    #pragma unroll
    for (int k = 0; k < 16; k++) {
        int i = t + k * 256;
        int c = i >> 6, o = i & 63;
        Wk[i] = (o < 20) ? Win[(320 + o) * 64 + c] : 0.0f;
    }
    __syncthreads();

    if (oo * 8 < 20) {
        ull acc[8][4];
        #pragma unroll
        for (int o = 0; o < 8; o++)
            #pragma unroll
            for (int j = 0; j < 4; j++) acc[o][j] = 0ull;

        #pragma unroll 4
        for (int c = 0; c < 64; c++) {
            float4 xa  = *(const float4*)(xs + c * 256 + po * 4);
            float4 xb4 = *(const float4*)(xs + c * 256 + po * 4 + 128);
            ull x0 = pk(xa.x, xa.y),   x1 = pk(xa.z, xa.w);
            ull x2 = pk(xb4.x, xb4.y), x3 = pk(xb4.z, xb4.w);
            float4 wa = *(const float4*)(Wk + c * 64 + oo * 8);
            float4 wb = *(const float4*)(Wk + c * 64 + oo * 8 + 4);
            float wv[8] = {wa.x, wa.y, wa.z, wa.w, wb.x, wb.y, wb.z, wb.w};
            #pragma unroll
            for (int o = 0; o < 8; o++) {
                ull wd = pk(wv[o], wv[o]);
                fma2(acc[o][0], wd, x0);
                fma2(acc[o][1], wd, x1);
                fma2(acc[o][2], wd, x2);
                fma2(acc[o][3], wd, x3);
            }
        }

        #pragma unroll
        for (int o = 0; o < 8; o++) {
            int og = 320 + oo * 8 + o;
            if (og < 340) {
                float2 p0 = upk(acc[o][0]), p1 = upk(acc[o][1]);
                float2 p2 = upk(acc[o][2]), p3 = upk(acc[o][3]);
                size_t pl = ((size_t)b * 340 + og) * 65536;
                *(float4*)(g_yr + pl + (size_t)(row0 + rA) * 256 + col0 + cA) =
                    make_float4(p0.x, p0.y, p1.x, p1.y);
                *(float4*)(g_yr + pl + (size_t)(row0 + rA + 2) * 256 + col0 + cA) =
                    make_float4(p2.x, p2.y, p3.x, p3.y);
            }
        }
    }
}

// ---------------------------------------------------------------------------
// Fallback kernel A (quant != ones): fused proj_in + DCT + quant + IDCT.
// ---------------------------------------------------------------------------
__global__ void __launch_bounds__(256, 2) kernA(
    const float* __restrict__ x, const float* __restrict__ Win,
    const float* __restrict__ quant)
{
    if (*(volatile int*)&g_ones) return;

    extern __shared__ float sm[];
    float* xs   = sm;
    float* bufA = sm + 16384;
    float* bufB = sm + 18688;
    float* Wk   = sm + 20992;
    float* qk   = sm + 21504;
    float* Ms   = sm + 22016;

    const int t  = threadIdx.x;
    const int b  = blockIdx.z;
    const int tx = blockIdx.x, ty = blockIdx.y;
    const int lx = t & 15, ly = t >> 4;
    const int gx = tx * 16 + lx, gy = ty * 16 + ly;

    if (t < 64) {
        int i = t >> 3, j = t & 7;
        Ms[t] = (i == 0) ? 0.3535533905932738f
                         : 0.5f * cosf((float)M_PI * (float)(i * (2 * j + 1)) / 16.0f);
    }
    {
        const float* xb = x + ((size_t)b << 22);
        int pofs = gy * 256 + gx;
        #pragma unroll
        for (int c = 0; c < 64; c++)
            xs[c * 256 + t] = xb[c * 65536 + pofs];
    }

    const int ch  = t >> 5;
    const int pat = (t >> 3) & 3;
    const int ln  = t & 7;
    float* pA = bufA + ch * 288 + pat * 72;
    float* pB = bufB + ch * 288 + pat * 72;

    const int patc = ((ly >> 3) << 1) + (lx >> 3);
    const int rr = ly & 7, cc = lx & 7;
    float* convDst = bufA + patc * 72 + rr * 9 + cc;

    for (int o0 = 0; o0 < 340; o0 += 8) {
        #pragma unroll
        for (int r = 0; r < 2; r++) {
            int idx = t + r * 256;
            int c = idx >> 3, o = idx & 7;
            Wk[idx] = (o0 + o < 340) ? Win[(o0 + o) * 64 + c] : 0.0f;
            int o2 = idx >> 6, rc = idx & 63;
            qk[idx] = (o0 + o2 < 340) ? quant[(o0 + o2) * 64 + rc] : 0.0f;
        }
        __syncthreads();

        float acc[8] = {0.f, 0.f, 0.f, 0.f, 0.f, 0.f, 0.f, 0.f};
        #pragma unroll 8
        for (int c = 0; c < 64; c++) {
            float  xv = xs[c * 256 + t];
            float4 w0 = *reinterpret_cast<const float4*>(Wk + c * 8);
            float4 w1 = *reinterpret_cast<const float4*>(Wk + c * 8 + 4);
            acc[0] += w0.x * xv; acc[1] += w0.y * xv;
            acc[2] += w0.z * xv; acc[3] += w0.w * xv;
            acc[4] += w1.x * xv; acc[5] += w1.y * xv;
            acc[6] += w1.z * xv; acc[7] += w1.w * xv;
        }
        #pragma unroll
        for (int o = 0; o < 8; o++) convDst[o * 288] = acc[o];
        __syncthreads();

        float v[8];
        #pragma unroll
        for (int p = 0; p < 8; p++) v[p] = pA[p * 9 + ln];
        #pragma unroll
        for (int i = 0; i < 8; i++) {
            float s = 0.f;
            #pragma unroll
            for (int p = 0; p < 8; p++) s += Ms[i * 8 + p] * v[p];
            pB[i * 9 + ln] = s;
        }
        __syncthreads();

        #pragma unroll
        for (int q = 0; q < 8; q++) v[q] = pB[ln * 9 + q];
        #pragma unroll
        for (int j = 0; j < 8; j++) {
            float s = 0.f;
            #pragma unroll
            for (int q = 0; q < 8; q++) s += v[q] * Ms[j * 8 + q];
            pA[ln * 9 + j] = s * qk[ch * 64 + ln * 8 + j];
        }
        __syncthreads();

        #pragma unroll
        for (int p = 0; p < 8; p++) v[p] = pA[p * 9 + ln];
        #pragma unroll
        for (int i = 0; i < 8; i++) {
            float s = 0.f;
            #pragma unroll
            for (int p = 0; p < 8; p++) s += Ms[p * 8 + i] * v[p];
            pB[i * 9 + ln] = s;
        }
        __syncthreads();

        #pragma unroll
        for (int q = 0; q < 8; q++) v[q] = pB[ln * 9 + q];
        int o = o0 + ch;
        if (o < 340) {
            float r8[8];
            #pragma unroll
            for (int j = 0; j < 8; j++) {
                float s = 0.f;
                #pragma unroll
                for (int q = 0; q < 8; q++) s += v[q] * Ms[q * 8 + j];
                r8[j] = s;
            }
            int py = pat >> 1, px = pat & 1;
            size_t base = (((size_t)b * 340 + o) * 256 +
                           (size_t)(ty * 16 + py * 8 + ln)) * 256 +
                          (size_t)(tx * 16 + px * 8);
            float4* dst = reinterpret_cast<float4*>(g_yr + base);
            dst[0] = make_float4(r8[0], r8[1], r8[2], r8[3]);
            dst[1] = make_float4(r8[4], r8[5], r8[6], r8[7]);
        }
    }
}

// ---------------------------------------------------------------------------
// Kernel B9: fused depthwise 3x3 + exact-GELU gate + proj_out.
// B5 pipeline (2 pairs/round, 4 stages, wait_group 2) with 16-byte cp.async
// halo staging: each plane staged as 18 rows x 32 floats (aligned span
// [col0-4, col0+28)), smem row stride 48 floats. Border chunks zero-filled
// realize the conv's zero padding.
// Dyn smem (floats): Wo 10880 | pdwu 1700 ull = 3400 | tb 4x4x18x48 = 13824
//   -> 14280 + 13824 = 28104 floats = 112416 B. occ 2.
// ---------------------------------------------------------------------------
__global__ void __launch_bounds__(256, 2) kernB9(
    const float* __restrict__ Wdw, const float* __restrict__ Wout,
    float* __restrict__ out)
{
    extern __shared__ float smB[];
    float* Wo   = smB;                      // [oh][64]           (10880 floats)
    ull*   pdwu = (ull*)(smB + 10880);      // [oh][10] packed    (3400 floats)
    float* tb   = smB + 14280;              // [4][4][18][48]     (13824 floats)

    const int t  = threadIdx.x;
    const int b  = blockIdx.z;
    const int tx = blockIdx.x, ty = blockIdx.y;
    const int lx = t & 15, ly = t >> 4;
    const int gx = tx * 16 + lx, gy = ty * 16 + ly;

    for (int i = t; i < 10880; i += 256)
        Wo[i] = Wout[(i & 63) * 170 + (i >> 6)];
    for (int i = t; i < 1530; i += 256) {
        int oh = i / 9, k = i - oh * 9;
        pdwu[oh * 10 + k] = pk(Wdw[oh * 9 + k], Wdw[(oh + 170) * 9 + k]);
    }

    // --- cp16 slot geometry (static per thread; 3 slots, slot 2 iff t<64) ---
    // q in [0,576): plane = q/144, row = (q%144)/8, c4 = q%8.
    // plane: pair = plane>>1, half = plane&1 -> channel add = pair + half*170.
    const uint64_t yrb = gmem_u64(g_yr) + (uint64_t)b * 340 * 262144ull;
    const uint32_t tbu = smem_u32(tb);

    uint32_t dsto[3];
    uint64_t poso[3];
    unsigned szo[3];
    uint32_t chA[3];
    #pragma unroll
    for (int m = 0; m < 3; m++) {
        int q = t + m * 256;
        if (q < 576) {
            int pl = q / 144, rc = q % 144;
            int row = rc >> 3, c4 = rc & 7;
            chA[m] = (uint32_t)((pl >> 1) + (pl & 1) * 170);
            int y  = ty * 16 - 1 + row;
            int xs_ = tx * 16 - 4 + c4 * 4;
            bool ok = ((unsigned)y < 256u) && (xs_ >= 0) && (xs_ <= 252);
            poso[m] = ok ? ((uint64_t)(y * 256 + xs_) * 4ull) : 0ull;
            szo[m]  = ok ? 16u : 0u;
            dsto[m] = (uint32_t)((pl * 864 + row * 48) * 4 + c4 * 16);
        } else {
            chA[m] = 0; poso[m] = 0; szo[m] = 0; dsto[m] = 0;
        }
    }
    const bool hv3 = (t < 64);

    // Round r loads channels (2r, 2r+1) x 2 halves into stage r&3.
    auto load_round = [&](int r) {
        uint32_t sb = tbu + (uint32_t)(r & 3) * 13824u;   // stage stride, bytes
        cp16(sb + dsto[0], yrb + (uint64_t)(2 * r + chA[0]) * 262144ull + poso[0], szo[0]);
        cp16(sb + dsto[1], yrb + (uint64_t)(2 * r + chA[1]) * 262144ull + poso[1], szo[1]);
        if (hv3)
            cp16(sb + dsto[2], yrb + (uint64_t)(2 * r + chA[2]) * 262144ull + poso[2], szo[2]);
    };

    load_round(0); cp_commit();
    load_round(1); cp_commit();
    load_round(2); cp_commit();

    ull acc[32];
    #pragma unroll
    for (int j = 0; j < 32; j++) acc[j] = 0ull;

    const ulonglong2* Wo2 = (const ulonglong2*)Wo;
    const int tap0 = ly * 48 + lx + 3;      // row ly, col lx+3

    for (int r = 0; r < 85; r++) {
        cp_wait2();
        __syncthreads();

        if (r + 3 < 85) load_round(r + 3);
        cp_commit();

        const float* stg = tb + (r & 3) * 3456;           // stage stride, floats
        #pragma unroll
        for (int pr = 0; pr < 2; pr++) {
            int oh = 2 * r + pr;
            const float* t1 = stg + pr * 1728;            // half-0 plane
            const float* t2 = t1 + 864;                   // half-1 plane

            const ulonglong2* pw2 = (const ulonglong2*)(pdwu + oh * 10);
            ulonglong2 w01 = pw2[0], w23 = pw2[1], w45 = pw2[2], w67 = pw2[3];
            ull w8 = pdwu[oh * 10 + 8];
            ull wk[9] = {w01.x, w01.y, w23.x, w23.y, w45.x, w45.y, w67.x, w67.y, w8};

            ull d2 = 0ull;
            #pragma unroll
            for (int ky = 0; ky < 3; ky++) {
                int ro = tap0 + ky * 48;
                #pragma unroll
                for (int kx = 0; kx < 3; kx++) {
                    ull v = pk(t1[ro + kx], t2[ro + kx]);
                    fma2(d2, v, wk[ky * 3 + kx]);
                }
            }
            float2 d = upk(d2);
            float g = 0.5f * d.x * (1.0f + erff(d.x * 0.7071067811865476f)) * d.y;
            ull gg = pk(g, g);

            #pragma unroll
            for (int j4 = 0; j4 < 16; j4++) {
                ulonglong2 w2 = Wo2[oh * 16 + j4];
                fma2(acc[j4 * 2 + 0], gg, w2.x);
                fma2(acc[j4 * 2 + 1], gg, w2.y);
            }
        }
    }

    size_t obase = ((size_t)b * 64) * 65536 + (size_t)gy * 256 + (size_t)gx;
    #pragma unroll
    for (int j = 0; j < 32; j++) {
        float2 v = upk(acc[j]);
        out[obase + (size_t)(j * 2 + 0) * 65536] = v.x;
        out[obase + (size_t)(j * 2 + 1) * 65536] = v.y;
    }
}

// ---------------------------------------------------------------------------
extern "C" void kernel_launch(void* const* d_in, const int* in_sizes, int n_in,
                              void* d_out, int out_size)
{
    (void)in_sizes; (void)n_in; (void)out_size;
    const float* x     = (const float*)d_in[0];  // [4,64,256,256]
    const float* Win   = (const float*)d_in[1];  // [340,64]
    const float* Wdw   = (const float*)d_in[2];  // [340,1,3,3]
    const float* quant = (const float*)d_in[3];  // [340,1,1,8,8]
    const float* Wout  = (const float*)d_in[4];  // [64,170]
    float* out = (float*)d_out;                  // [4,64,256,256]

    static int attr_done = 0;
    if (!attr_done) {
        cudaFuncSetAttribute(kernA,  cudaFuncAttributeMaxDynamicSharedMemorySize, 88320);
        cudaFuncSetAttribute(kernA2, cudaFuncAttributeMaxDynamicSharedMemorySize, 81920);
        cudaFuncSetAttribute(kernB9, cudaFuncAttributeMaxDynamicSharedMemorySize, 112416);
        attr_done = 1;
    }

    kinit<<<1, 32>>>();
    kcheck<<<85, 256>>>(quant);

    dim3 gOld(16, 16, 4), blk(256);
    kernA<<<gOld, blk, 88320>>>(x, Win, quant);   // runs only if quant != 1

    dim3 gA2(4, 64, 4);
    kernA2<<<gA2, blk, 81920>>>(x, Win);          // runs only if quant == 1

    kernB9<<<gOld, blk, 112416>>>(Wdw, Wout, out);
}